// round 5
// baseline (speedup 1.0000x reference)
#include <cuda_runtime.h>
#include <math.h>

#define NRC 1024
#define NN  (NRC * NRC)
#define HL  (NRC * (NRC - 1))
#define NB  128          // blocks (all co-resident: 128 <= 148 SMs)
#define TPB 1024
#define RPB 8            // rows per block

// ---------------- device scratch (no allocation) ----------------
__device__ float  d_R [NN];              // CG residual r
__device__ float  d_AP[NN];              // A*p
__device__ float  d_X [NN];              // CG solution x (potential)
__device__ float  d_gh[NN];              // g halo (stage setup only)
__device__ float  d_ph[NN];              // initial p (=b) halo (stage setup only)
__device__ float  d_hr [2][NB * 2][NRC]; // published boundary r   (double-buffered)
__device__ float  d_hAp[2][NB * 2][NRC]; // published boundary Ap  (double-buffered)
__device__ double d_pA[3][NB];           // partials (slot 2 = stage setup ||b||^2)
__device__ double d_pB[3][NB];
__device__ double d_pC[3][NB];
__device__ unsigned d_cnt = 0;           // barrier arrival count (self-resetting)
__device__ unsigned d_gen = 0;           // barrier generation (monotonic, replay-safe)

// ---------------- PROVEN grid barrier (R2 verbatim) ----------------
__device__ __forceinline__ void grid_bar() {
    __threadfence();
    __syncthreads();
    if (threadIdx.x == 0) {
        unsigned g = atomicAdd(&d_gen, 0u);
        if (atomicAdd(&d_cnt, 1u) == NB - 1u) {
            atomicExch(&d_cnt, 0u);
            __threadfence();
            atomicAdd(&d_gen, 1u);
        } else {
            while (atomicAdd(&d_gen, 0u) == g) { __nanosleep(64); }
            __threadfence();
        }
    }
    __syncthreads();
}

__device__ __forceinline__ double warp_red(double v) {
#pragma unroll
    for (int o = 16; o > 0; o >>= 1) v += __shfl_down_sync(0xffffffffu, v, o);
    return v;
}

__device__ __forceinline__ void block_red_store3(double a, double bb, double c,
                                                 double* A, double* B, double* C, int b) {
    __shared__ double swA[32], swB[32], swC[32];
    a  = warp_red(a);
    bb = warp_red(bb);
    c  = warp_red(c);
    int lane = threadIdx.x & 31, w = threadIdx.x >> 5;
    if (lane == 0) { swA[w] = a; swB[w] = bb; swC[w] = c; }
    __syncthreads();
    if (w == 0) {
        double v = warp_red(swA[lane]);
        if (lane == 0) __stcg(&A[b], v);
    } else if (w == 1) {
        double v = warp_red(swB[lane]);
        if (lane == 0) __stcg(&B[b], v);
    } else if (w == 2) {
        double v = warp_red(swC[lane]);
        if (lane == 0) __stcg(&C[b], v);
    }
}

__device__ __forceinline__ void red_finish3(const double* A, const double* B, const double* C,
                                            double& oA, double& oB, double& oC) {
    __shared__ double s12[12];
    __shared__ double bc[3];
    int t = threadIdx.x;
    if (t < 3 * NB) {
        int comp = t >> 7;
        int idx  = t & (NB - 1);
        const double* src = (comp == 0) ? A : (comp == 1) ? B : C;
        double v = __ldcg(src + idx);
        v = warp_red(v);
        if ((t & 31) == 0) s12[t >> 5] = v;
    }
    __syncthreads();
    if (t < 3) bc[t] = s12[t * 4] + s12[t * 4 + 1] + s12[t * 4 + 2] + s12[t * 4 + 3];
    __syncthreads();
    oA = bc[0]; oB = bc[1]; oC = bc[2];
}

__global__ void __launch_bounds__(TPB, 1)
conduit_persist(const float* __restrict__ conduit, const float* __restrict__ discharge,
                const float* __restrict__ geo,     const float* __restrict__ sv,
                const float* __restrict__ ll,      const float* __restrict__ fw,
                const float* __restrict__ area,    const int* __restrict__ status,
                float* __restrict__ out)
{
    // p (search direction) with ghost rows 0 and RPB+1; rows 1..RPB are own rows
    __shared__ float P[(RPB + 2) * NRC];   // 40 KB

    const int t  = threadIdx.x;            // column
    const int b  = blockIdx.x;
    const int r0 = b * RPB;

    const float fw0 = __ldg(fw), ll0 = __ldg(ll), ar0 = __ldg(area);
    const float coefb = fw0 / ar0;             // flux_div face coeff
    const float coefA = fw0 / (ll0 * ar0);     // laplace coeff

    // ---- gap_base (one-time; cold registers, may spill harmlessly) ----
    float gap[RPB];
#pragma unroll
    for (int j = 0; j < RPB; j++) {
        int row = r0 + j, i = row * NRC + t;
        float s = 0.f, n = 0.f;
        if (t   < NRC - 1) { s += __ldg(&sv[row * (NRC - 1) + t]);     n += 1.f; }
        if (t   > 0)       { s += __ldg(&sv[row * (NRC - 1) + t - 1]); n += 1.f; }
        if (row < NRC - 1) { s += __ldg(&sv[HL + i]);                  n += 1.f; }
        if (row > 0)       { s += __ldg(&sv[HL + i - NRC]);            n += 1.f; }
        float sl = (s * (1.0f / 31556926.0f)) / fmaxf(n, 1.0f);
        gap[j] = fabsf(sl) * 0.03f;
    }

    float kk[RPB], ksum[RPB];
#pragma unroll
    for (int j = 0; j < RPB; j++) { kk[j] = 0.f; ksum[j] = 0.f; }

    const float coefs[4] = {0.f, 1800.f, 1800.f, 3600.f};
    const int slotN = b * 2;               // my north boundary slot (row r0)
    const int slotS = b * 2 + 1;           // my south boundary slot (row r0+7)

    for (int s = 0; s < 4; s++) {
        const float cst = coefs[s];

        // ---- setup 1: S, g -> P rows 1..8 (+ halo rows to d_gh) ----
#pragma unroll
        for (int j = 0; j < RPB; j++) {
            int row = r0 + j, i = row * NRC + t;
            float S = __ldg(&conduit[i]) + cst * kk[j];
            float g = __ldg(&discharge[i]) * 0.0405f * (S * sqrtf(sqrtf(S)));
            g = g * g;
            P[(j + 1) * NRC + t] = g;
            if (j == 0 || j == RPB - 1) __stcg(&d_gh[i], g);
        }
        grid_bar();   // setup bar 1

        // ghost g rows (same-thread write/read; grid_bar synced publishers)
        if (b > 0)      P[0 * NRC + t]         = __ldcg(&d_gh[(r0 - 1)   * NRC + t]);
        if (b < NB - 1) P[(RPB + 1) * NRC + t] = __ldcg(&d_gh[(r0 + RPB) * NRC + t]);

        // ---- setup 2: b = flux_div(g_link); r = p = b; x = 0; ||b||^2 ----
        double dacc = 0.0;
        float bv[RPB];
#pragma unroll
        for (int j = 0; j < RPB; j++) {
            int row = r0 + j, i = row * NRC + t;
            int   sti  = __ldg(&status[i]);
            float gi   = P[(j + 1) * NRC + t];
            float geoi = __ldg(&geo[i]);
            float acc  = 0.f;
            if (t < NRC - 1) {             // east link (i tail): +
                int jn = i + 1;
                acc += ((sti | __ldg(&status[jn])) != 0)
                     ? 0.5f * (geoi + __ldg(&geo[jn]))
                     : 0.5f * (gi + P[(j + 1) * NRC + t + 1]);
            }
            if (t > 0) {                   // west link (i head): -
                int jn = i - 1;
                acc -= ((sti | __ldg(&status[jn])) != 0)
                     ? 0.5f * (geoi + __ldg(&geo[jn]))
                     : 0.5f * (gi + P[(j + 1) * NRC + t - 1]);
            }
            if (row < NRC - 1) {           // south link (i tail): +
                int jn = i + NRC;
                float gn = P[(j + 2) * NRC + t];
                acc += ((sti | __ldg(&status[jn])) != 0)
                     ? 0.5f * (geoi + __ldg(&geo[jn]))
                     : 0.5f * (gi + gn);
            }
            if (row > 0) {                 // north link (i head): -
                int jn = i - NRC;
                float gn = P[j * NRC + t];
                acc -= ((sti | __ldg(&status[jn])) != 0)
                     ? 0.5f * (geoi + __ldg(&geo[jn]))
                     : 0.5f * (gi + gn);
            }
            float v = coefb * acc;
            bv[j] = v;
            __stcg(&d_R[i], v);
            __stcg(&d_X[i], 0.f);
            dacc += (double)v * (double)v;
        }
        __syncthreads();                   // g reads done before overwriting P with p
#pragma unroll
        for (int j = 0; j < RPB; j++) {
            int i = (r0 + j) * NRC + t;
            P[(j + 1) * NRC + t] = bv[j];
            if (j == 0 || j == RPB - 1) __stcg(&d_ph[i], bv[j]);
        }
        block_red_store3(dacc, 0.0, 0.0, d_pA[2], d_pB[2], d_pC[2], b);
        grid_bar();   // setup bar 2

        // ghost p init (= neighbor boundary b)
        if (b > 0)      P[0 * NRC + t]         = __ldcg(&d_ph[(r0 - 1)   * NRC + t]);
        if (b < NB - 1) P[(RPB + 1) * NRC + t] = __ldcg(&d_ph[(r0 + RPB) * NRC + t]);

        double bnorm2, duB, duC;
        red_finish3(d_pA[2], d_pB[2], d_pC[2], bnorm2, duB, duC);
        double rs    = bnorm2;
        double atol2 = 1e-6 * bnorm2;      // CG_TOL^2 * ||b||^2

        // ---- CG loop: ONE barrier per iteration; no hot register arrays ----
        for (int it = 0; it < 64; ++it) {
            if (!(rs > atol2)) break;
            const int buf = it & 1;

            // SpMV (rolling window down the column) + three dots
            double pap = 0.0, rap = 0.0, apap = 0.0;
            float pubRn = 0.f, pubApN = 0.f, pubRS = 0.f, pubApS = 0.f;
            float pN = P[0 * NRC + t];
            float pc = P[1 * NRC + t];
#pragma unroll
            for (int j = 0; j < RPB; j++) {
                int row = r0 + j, i = row * NRC + t;
                float pS = P[(j + 2) * NRC + t];
                float sum = 0.f, deg = 0.f;
                if (t > 0)         { sum += P[(j + 1) * NRC + t - 1]; deg += 1.f; }
                if (t < NRC - 1)   { sum += P[(j + 1) * NRC + t + 1]; deg += 1.f; }
                if (row > 0)       { sum += pN; deg += 1.f; }
                if (row < NRC - 1) { sum += pS; deg += 1.f; }
                float ap = coefA * (sum - deg * pc);
                float rv = __ldcg(&d_R[i]);
                __stcg(&d_AP[i], ap);
                pap  += (double)pc * (double)ap;
                rap  += (double)rv * (double)ap;
                apap += (double)ap * (double)ap;
                if (j == 0)       { pubRn = rv; pubApN = ap; }
                if (j == RPB - 1) { pubRS = rv; pubApS = ap; }
                pN = pc; pc = pS;
            }
            // publish boundary r_k and Ap_k (pre-update values) for neighbors
            __stcg(&d_hr [buf][slotN][t], pubRn);
            __stcg(&d_hAp[buf][slotN][t], pubApN);
            __stcg(&d_hr [buf][slotS][t], pubRS);
            __stcg(&d_hAp[buf][slotS][t], pubApS);

            block_red_store3(pap, rap, apap, d_pA[buf], d_pB[buf], d_pC[buf], b);
            grid_bar();   // the ONLY barrier this iteration

            double paps, raps, apaps;
            red_finish3(d_pA[buf], d_pB[buf], d_pC[buf], paps, raps, apaps);

            double alpha  = rs / paps;
            double rs_new = rs - 2.0 * alpha * raps + alpha * alpha * apaps;
            if (rs_new < 0.0) rs_new = 0.0;
            float  af = (float)alpha;
            float  bf = (float)(rs_new / rs);

            // fused update: x += a p ; r -= a Ap ; p = r + beta p
#pragma unroll
            for (int j = 0; j < RPB; j++) {
                int i = (r0 + j) * NRC + t;
                float pcv = P[(j + 1) * NRC + t];
                __stcg(&d_X[i], __ldcg(&d_X[i]) + af * pcv);
                float rn = __ldcg(&d_R[i]) - af * __ldcg(&d_AP[i]);
                __stcg(&d_R[i], rn);
                P[(j + 1) * NRC + t] = rn + bf * pcv;
            }
            // advance ghost p with IDENTICAL float-op order as neighbor's update
            if (b > 0) {
                float hr  = __ldcg(&d_hr [buf][slotN - 1][t]);
                float hap = __ldcg(&d_hAp[buf][slotN - 1][t]);
                float rn  = hr - af * hap;
                P[0 * NRC + t] = rn + bf * P[0 * NRC + t];
            }
            if (b < NB - 1) {
                float hr  = __ldcg(&d_hr [buf][slotS + 1][t]);
                float hap = __ldcg(&d_hAp[buf][slotS + 1][t]);
                float rn  = hr - af * hap;
                P[(RPB + 1) * NRC + t] = rn + bf * P[(RPB + 1) * NRC + t];
            }
            rs = rs_new;
            __syncthreads();   // p writes visible to t+-1 before next SpMV
        }

        // ---- stage end: roc, RK accumulation ----
#pragma unroll
        for (int j = 0; j < RPB; j++) {
            int i = (r0 + j) * NRC + t;
            float c = __ldg(&conduit[i]);
            float q = __ldg(&discharge[i]);
            float S = c + cst * kk[j];
            float g = q * 0.0405f * (S * sqrtf(sqrtf(S)));
            g = g * g;
            float pres = __ldg(&geo[i]) - __ldcg(&d_X[i]);
            float nk = 1.3455e-9f * q * g
                     + gap[j] * (1.0f - tanhf(S * (1.0f / 5.74f)))
                     - 7.11e-24f * pres * pres * pres * S;
            if (s == 0)      ksum[j] = nk;
            else if (s == 3) out[i]  = c + 600.0f * (ksum[j] + nk);
            else             ksum[j] += 2.0f * nk;
            kk[j] = nk;
        }
    }
}

extern "C" void kernel_launch(void* const* d_in, const int* in_sizes, int n_in,
                              void* d_out, int out_size) {
    const float* conduit   = (const float*)d_in[0];
    const float* discharge = (const float*)d_in[1];
    const float* geo       = (const float*)d_in[2];
    const float* sv        = (const float*)d_in[3];
    const float* ll        = (const float*)d_in[4];
    const float* fw        = (const float*)d_in[5];
    const float* area      = (const float*)d_in[6];
    const int*   status    = (const int*)  d_in[9];
    float* out = (float*)d_out;

    conduit_persist<<<NB, TPB>>>(conduit, discharge, geo, sv, ll, fw, area, status, out);
}

// round 6
// speedup vs baseline: 1.0745x; 1.0745x over previous
#include <cuda_runtime.h>
#include <math.h>

#define NRC 1024
#define NN  (NRC * NRC)
#define HL  (NRC * (NRC - 1))
#define NB  128          // blocks (all co-resident: 128 <= 148 SMs)
#define TPB 1024
#define RPB 8            // rows per block

// dynamic shared layout (floats): P[(RPB+2)*NRC] | R[RPB*NRC] | X[RPB*NRC] | AP[RPB*NRC]
#define SMEM_FLOATS ((RPB + 2 + 3 * RPB) * NRC)   // 34816 floats = 139264 B

// ---------------- device scratch (no allocation) ----------------
__device__ float  d_gh[NN];              // g halo (stage setup only)
__device__ float  d_ph[NN];              // initial p (=b) halo (stage setup only)
__device__ float  d_hr [2][NB * 2][NRC]; // published boundary r   (double-buffered)
__device__ float  d_hAp[2][NB * 2][NRC]; // published boundary Ap  (double-buffered)
__device__ double d_pA[3][NB];           // partials (slot 2 = stage setup ||b||^2)
__device__ double d_pB[3][NB];
__device__ double d_pC[3][NB];
__device__ unsigned d_cnt = 0;           // barrier arrival count (self-resetting)
__device__ unsigned d_gen = 0;           // barrier generation (monotonic, replay-safe)

// ---------------- PROVEN grid barrier (R2 verbatim) ----------------
__device__ __forceinline__ void grid_bar() {
    __threadfence();
    __syncthreads();
    if (threadIdx.x == 0) {
        unsigned g = atomicAdd(&d_gen, 0u);
        if (atomicAdd(&d_cnt, 1u) == NB - 1u) {
            atomicExch(&d_cnt, 0u);
            __threadfence();
            atomicAdd(&d_gen, 1u);
        } else {
            while (atomicAdd(&d_gen, 0u) == g) { __nanosleep(64); }
            __threadfence();
        }
    }
    __syncthreads();
}

__device__ __forceinline__ double warp_red(double v) {
#pragma unroll
    for (int o = 16; o > 0; o >>= 1) v += __shfl_down_sync(0xffffffffu, v, o);
    return v;
}

__device__ __forceinline__ void block_red_store3(double a, double bb, double c,
                                                 double* A, double* B, double* C, int b) {
    __shared__ double swA[32], swB[32], swC[32];
    a  = warp_red(a);
    bb = warp_red(bb);
    c  = warp_red(c);
    int lane = threadIdx.x & 31, w = threadIdx.x >> 5;
    if (lane == 0) { swA[w] = a; swB[w] = bb; swC[w] = c; }
    __syncthreads();
    if (w == 0) {
        double v = warp_red(swA[lane]);
        if (lane == 0) __stcg(&A[b], v);
    } else if (w == 1) {
        double v = warp_red(swB[lane]);
        if (lane == 0) __stcg(&B[b], v);
    } else if (w == 2) {
        double v = warp_red(swC[lane]);
        if (lane == 0) __stcg(&C[b], v);
    }
}

__device__ __forceinline__ void red_finish3(const double* A, const double* B, const double* C,
                                            double& oA, double& oB, double& oC) {
    __shared__ double s12[12];
    __shared__ double bc[3];
    int t = threadIdx.x;
    if (t < 3 * NB) {
        int comp = t >> 7;
        int idx  = t & (NB - 1);
        const double* src = (comp == 0) ? A : (comp == 1) ? B : C;
        double v = __ldcg(src + idx);
        v = warp_red(v);
        if ((t & 31) == 0) s12[t >> 5] = v;
    }
    __syncthreads();
    if (t < 3) bc[t] = s12[t * 4] + s12[t * 4 + 1] + s12[t * 4 + 2] + s12[t * 4 + 3];
    __syncthreads();
    oA = bc[0]; oB = bc[1]; oC = bc[2];
}

__global__ void __launch_bounds__(TPB, 1)
conduit_persist(const float* __restrict__ conduit, const float* __restrict__ discharge,
                const float* __restrict__ geo,     const float* __restrict__ sv,
                const float* __restrict__ ll,      const float* __restrict__ fw,
                const float* __restrict__ area,    const int* __restrict__ status,
                float* __restrict__ out)
{
    extern __shared__ float SH[];
    float* P  = SH;                       // (RPB+2) rows: ghosts at row 0 and RPB+1
    float* Rr = SH + (RPB + 2) * NRC;     // RPB rows
    float* X  = Rr + RPB * NRC;           // RPB rows
    float* AP = X  + RPB * NRC;           // RPB rows

    const int t  = threadIdx.x;           // column
    const int b  = blockIdx.x;
    const int r0 = b * RPB;

    const float fw0 = __ldg(fw), ll0 = __ldg(ll), ar0 = __ldg(area);
    const float coefb = fw0 / ar0;             // flux_div face coeff
    const float coefA = fw0 / (ll0 * ar0);     // laplace coeff

    // ---- gap_base (one-time; outside hot loop) ----
    float gap[RPB];
#pragma unroll
    for (int j = 0; j < RPB; j++) {
        int row = r0 + j, i = row * NRC + t;
        float s = 0.f, n = 0.f;
        if (t   < NRC - 1) { s += __ldg(&sv[row * (NRC - 1) + t]);     n += 1.f; }
        if (t   > 0)       { s += __ldg(&sv[row * (NRC - 1) + t - 1]); n += 1.f; }
        if (row < NRC - 1) { s += __ldg(&sv[HL + i]);                  n += 1.f; }
        if (row > 0)       { s += __ldg(&sv[HL + i - NRC]);            n += 1.f; }
        float sl = (s * (1.0f / 31556926.0f)) / fmaxf(n, 1.0f);
        gap[j] = fabsf(sl) * 0.03f;
    }

    float kk[RPB], ksum[RPB];
#pragma unroll
    for (int j = 0; j < RPB; j++) { kk[j] = 0.f; ksum[j] = 0.f; }

    const float coefs[4] = {0.f, 1800.f, 1800.f, 3600.f};
    const int slotN = b * 2;               // my north boundary slot (row r0)
    const int slotS = b * 2 + 1;           // my south boundary slot (row r0+7)

    for (int s = 0; s < 4; s++) {
        const float cst = coefs[s];

        // ---- setup 1: S, g -> P rows 1..8 (+ halo rows to d_gh) ----
#pragma unroll
        for (int j = 0; j < RPB; j++) {
            int row = r0 + j, i = row * NRC + t;
            float S = __ldg(&conduit[i]) + cst * kk[j];
            float g = __ldg(&discharge[i]) * 0.0405f * (S * sqrtf(sqrtf(S)));
            g = g * g;
            P[(j + 1) * NRC + t] = g;
            if (j == 0 || j == RPB - 1) __stcg(&d_gh[i], g);
        }
        grid_bar();   // setup bar 1

        // ghost g rows
        if (b > 0)      P[0 * NRC + t]         = __ldcg(&d_gh[(r0 - 1)   * NRC + t]);
        if (b < NB - 1) P[(RPB + 1) * NRC + t] = __ldcg(&d_gh[(r0 + RPB) * NRC + t]);

        // ---- setup 2: b = flux_div(g_link); r = p = b; x = 0; ||b||^2 ----
        double dacc = 0.0;
        float bv[RPB];
#pragma unroll
        for (int j = 0; j < RPB; j++) {
            int row = r0 + j, i = row * NRC + t;
            int   sti  = __ldg(&status[i]);
            float gi   = P[(j + 1) * NRC + t];
            float geoi = __ldg(&geo[i]);
            float acc  = 0.f;
            if (t < NRC - 1) {             // east link (i tail): +
                int jn = i + 1;
                acc += ((sti | __ldg(&status[jn])) != 0)
                     ? 0.5f * (geoi + __ldg(&geo[jn]))
                     : 0.5f * (gi + P[(j + 1) * NRC + t + 1]);
            }
            if (t > 0) {                   // west link (i head): -
                int jn = i - 1;
                acc -= ((sti | __ldg(&status[jn])) != 0)
                     ? 0.5f * (geoi + __ldg(&geo[jn]))
                     : 0.5f * (gi + P[(j + 1) * NRC + t - 1]);
            }
            if (row < NRC - 1) {           // south link (i tail): +
                int jn = i + NRC;
                float gn = P[(j + 2) * NRC + t];
                acc += ((sti | __ldg(&status[jn])) != 0)
                     ? 0.5f * (geoi + __ldg(&geo[jn]))
                     : 0.5f * (gi + gn);
            }
            if (row > 0) {                 // north link (i head): -
                int jn = i - NRC;
                float gn = P[j * NRC + t];
                acc -= ((sti | __ldg(&status[jn])) != 0)
                     ? 0.5f * (geoi + __ldg(&geo[jn]))
                     : 0.5f * (gi + gn);
            }
            float v = coefb * acc;
            bv[j] = v;
            dacc += (double)v * (double)v;
        }
        __syncthreads();                   // g reads done before overwriting P with p
#pragma unroll
        for (int j = 0; j < RPB; j++) {
            int i = (r0 + j) * NRC + t;
            P[(j + 1) * NRC + t] = bv[j];
            Rr[j * NRC + t] = bv[j];
            X [j * NRC + t] = 0.f;
            if (j == 0 || j == RPB - 1) __stcg(&d_ph[i], bv[j]);
        }
        block_red_store3(dacc, 0.0, 0.0, d_pA[2], d_pB[2], d_pC[2], b);
        grid_bar();   // setup bar 2

        // ghost p init (= neighbor boundary b)
        if (b > 0)      P[0 * NRC + t]         = __ldcg(&d_ph[(r0 - 1)   * NRC + t]);
        if (b < NB - 1) P[(RPB + 1) * NRC + t] = __ldcg(&d_ph[(r0 + RPB) * NRC + t]);

        double bnorm2, duB, duC;
        red_finish3(d_pA[2], d_pB[2], d_pC[2], bnorm2, duB, duC);
        double rs    = bnorm2;
        double atol2 = 1e-6 * bnorm2;      // CG_TOL^2 * ||b||^2

        // ---- CG loop: ONE barrier per iteration; ALL state in shared ----
        for (int it = 0; it < 64; ++it) {
            if (!(rs > atol2)) break;
            const int buf = it & 1;

            // SpMV (rolling window down the column) + three dots
            double pap = 0.0, rap = 0.0, apap = 0.0;
            float pN = P[0 * NRC + t];
            float pc = P[1 * NRC + t];
#pragma unroll
            for (int j = 0; j < RPB; j++) {
                int row = r0 + j;
                float pS = P[(j + 2) * NRC + t];
                float sum = 0.f, deg = 0.f;
                if (t > 0)         { sum += P[(j + 1) * NRC + t - 1]; deg += 1.f; }
                if (t < NRC - 1)   { sum += P[(j + 1) * NRC + t + 1]; deg += 1.f; }
                if (row > 0)       { sum += pN; deg += 1.f; }
                if (row < NRC - 1) { sum += pS; deg += 1.f; }
                float ap = coefA * (sum - deg * pc);
                float rv = Rr[j * NRC + t];
                AP[j * NRC + t] = ap;
                pap  += (double)pc * (double)ap;
                rap  += (double)rv * (double)ap;
                apap += (double)ap * (double)ap;
                if (j == 0) {
                    __stcg(&d_hr [buf][slotN][t], rv);
                    __stcg(&d_hAp[buf][slotN][t], ap);
                }
                if (j == RPB - 1) {
                    __stcg(&d_hr [buf][slotS][t], rv);
                    __stcg(&d_hAp[buf][slotS][t], ap);
                }
                pN = pc; pc = pS;
            }

            block_red_store3(pap, rap, apap, d_pA[buf], d_pB[buf], d_pC[buf], b);
            grid_bar();   // the ONLY barrier this iteration (fence now drains ~4 stores)

            double paps, raps, apaps;
            red_finish3(d_pA[buf], d_pB[buf], d_pC[buf], paps, raps, apaps);

            double alpha  = rs / paps;
            double rs_new = rs - 2.0 * alpha * raps + alpha * alpha * apaps;
            if (rs_new < 0.0) rs_new = 0.0;
            float  af = (float)alpha;
            float  bf = (float)(rs_new / rs);

            // fused update: x += a p ; r -= a Ap ; p = r + beta p  (all smem)
#pragma unroll
            for (int j = 0; j < RPB; j++) {
                float pcv = P[(j + 1) * NRC + t];
                X[j * NRC + t] += af * pcv;
                float rn = Rr[j * NRC + t] - af * AP[j * NRC + t];
                Rr[j * NRC + t] = rn;
                P[(j + 1) * NRC + t] = rn + bf * pcv;
            }
            // advance ghost p with IDENTICAL float-op order as neighbor's update
            if (b > 0) {
                float hr  = __ldcg(&d_hr [buf][slotN - 1][t]);
                float hap = __ldcg(&d_hAp[buf][slotN - 1][t]);
                float rn  = hr - af * hap;
                P[0 * NRC + t] = rn + bf * P[0 * NRC + t];
            }
            if (b < NB - 1) {
                float hr  = __ldcg(&d_hr [buf][slotS + 1][t]);
                float hap = __ldcg(&d_hAp[buf][slotS + 1][t]);
                float rn  = hr - af * hap;
                P[(RPB + 1) * NRC + t] = rn + bf * P[(RPB + 1) * NRC + t];
            }
            rs = rs_new;
            __syncthreads();   // p writes visible to t+-1 before next SpMV
        }

        // ---- stage end: roc, RK accumulation ----
#pragma unroll
        for (int j = 0; j < RPB; j++) {
            int i = (r0 + j) * NRC + t;
            float c = __ldg(&conduit[i]);
            float q = __ldg(&discharge[i]);
            float S = c + cst * kk[j];
            float g = q * 0.0405f * (S * sqrtf(sqrtf(S)));
            g = g * g;
            float pres = __ldg(&geo[i]) - X[j * NRC + t];
            float nk = 1.3455e-9f * q * g
                     + gap[j] * (1.0f - tanhf(S * (1.0f / 5.74f)))
                     - 7.11e-24f * pres * pres * pres * S;
            if (s == 0)      ksum[j] = nk;
            else if (s == 3) out[i]  = c + 600.0f * (ksum[j] + nk);
            else             ksum[j] += 2.0f * nk;
            kk[j] = nk;
        }
        __syncthreads();   // protect P (g reuse) across stage boundary
    }
}

extern "C" void kernel_launch(void* const* d_in, const int* in_sizes, int n_in,
                              void* d_out, int out_size) {
    const float* conduit   = (const float*)d_in[0];
    const float* discharge = (const float*)d_in[1];
    const float* geo       = (const float*)d_in[2];
    const float* sv        = (const float*)d_in[3];
    const float* ll        = (const float*)d_in[4];
    const float* fw        = (const float*)d_in[5];
    const float* area      = (const float*)d_in[6];
    const int*   status    = (const int*)  d_in[9];
    float* out = (float*)d_out;

    static int configured = 0;
    if (!configured) {
        cudaFuncSetAttribute(conduit_persist,
                             cudaFuncAttributeMaxDynamicSharedMemorySize,
                             SMEM_FLOATS * (int)sizeof(float));
        configured = 1;
    }
    conduit_persist<<<NB, TPB, SMEM_FLOATS * sizeof(float)>>>(
        conduit, discharge, geo, sv, ll, fw, area, status, out);
}